// round 1
// baseline (speedup 1.0000x reference)
#include <cuda_runtime.h>
#include <math.h>

#define Bn   8
#define Hh   128
#define Wd   128
#define Cc   192
#define Gg   6
#define GC   32
#define KK2  9
#define NOFF 108     // G*K2*2
#define NMSK 54      // G*K2
#define M_PIX (Bn*Hh*Wd)   // 131072

// Scratch (device globals — no runtime allocation allowed)
__device__ float g_xproj[(size_t)M_PIX * Cc];
__device__ float g_xd   [(size_t)M_PIX * Cc];
__device__ float g_tmp  [(size_t)M_PIX * Cc];   // dw output, later reused as sampled output
__device__ float g_off  [(size_t)M_PIX * NOFF];
__device__ float g_msk  [(size_t)M_PIX * NMSK];

// ---------------------------------------------------------------------------
// Tiled SGEMM: C[M,N] = A[M,K] @ W[K,N] + bias[N]
// BM=128, BN=64, BK=16, 256 threads, 8x4 micro-tile per thread.
// K must be a multiple of 16 and M a multiple of 128 (true here: K=192, M=131072).
// N may be arbitrary (guarded B loads/stores).
// ---------------------------------------------------------------------------
__global__ __launch_bounds__(256) void sgemm_bias(
    const float* __restrict__ A, const float* __restrict__ W,
    const float* __restrict__ bias, float* __restrict__ C,
    int M, int N, int K)
{
    const int BM = 128, BN = 64, BK = 16;
    __shared__ float As[BK][BM];
    __shared__ float Bs[BK][BN];

    const int bm = blockIdx.y * BM;
    const int bn = blockIdx.x * BN;
    const int tid = threadIdx.x;
    const int tx = tid & 15;   // col group: 16 * 4 = 64 cols
    const int ty = tid >> 4;   // row group: 16 * 8 = 128 rows

    float acc[8][4];
#pragma unroll
    for (int i = 0; i < 8; i++)
#pragma unroll
        for (int j = 0; j < 4; j++) acc[i][j] = 0.f;

    for (int k0 = 0; k0 < K; k0 += BK) {
        // Load A tile (BM x BK) as float4 along K, store transposed.
#pragma unroll
        for (int i = tid; i < BM * BK / 4; i += 256) {
            int row = i >> 2;          // /(BK/4)
            int kq  = i & 3;
            float4 v = *reinterpret_cast<const float4*>(
                &A[(size_t)(bm + row) * K + k0 + kq * 4]);
            As[kq * 4 + 0][row] = v.x;
            As[kq * 4 + 1][row] = v.y;
            As[kq * 4 + 2][row] = v.z;
            As[kq * 4 + 3][row] = v.w;
        }
        // Load B tile (BK x BN), scalar (N may be unaligned, e.g. 54).
#pragma unroll
        for (int i = tid; i < BK * BN; i += 256) {
            int kk = i >> 6;           // / BN
            int nn = i & 63;
            int ncol = bn + nn;
            Bs[kk][nn] = (ncol < N) ? W[(size_t)(k0 + kk) * N + ncol] : 0.f;
        }
        __syncthreads();

#pragma unroll
        for (int kk = 0; kk < BK; kk++) {
            float ra[8], rb[4];
#pragma unroll
            for (int i = 0; i < 8; i++) ra[i] = As[kk][ty * 8 + i];
#pragma unroll
            for (int j = 0; j < 4; j++) rb[j] = Bs[kk][tx * 4 + j];
#pragma unroll
            for (int i = 0; i < 8; i++)
#pragma unroll
                for (int j = 0; j < 4; j++)
                    acc[i][j] = fmaf(ra[i], rb[j], acc[i][j]);
        }
        __syncthreads();
    }

#pragma unroll
    for (int i = 0; i < 8; i++) {
        int row = bm + ty * 8 + i;
#pragma unroll
        for (int j = 0; j < 4; j++) {
            int col = bn + tx * 4 + j;
            if (col < N)
                C[(size_t)row * N + col] = acc[i][j] + bias[col];
        }
    }
}

// ---------------------------------------------------------------------------
// Depthwise 3x3 'SAME' conv (zero pad) + bias + SiLU. Channels-last.
// ---------------------------------------------------------------------------
__global__ __launch_bounds__(256) void dw_silu(
    const float* __restrict__ x, const float* __restrict__ wdw,
    const float* __restrict__ bdw, float* __restrict__ out)
{
    size_t idx = (size_t)blockIdx.x * blockDim.x + threadIdx.x;
    if (idx >= (size_t)M_PIX * Cc) return;
    int c = (int)(idx % Cc);
    int p = (int)(idx / Cc);
    int w = p % Wd;
    int h = (p / Wd) % Hh;
    int b = p / (Wd * Hh);

    float acc = bdw[c];
#pragma unroll
    for (int ky = 0; ky < 3; ky++) {
        int hy = h + ky - 1;
        if (hy < 0 || hy >= Hh) continue;
#pragma unroll
        for (int kx = 0; kx < 3; kx++) {
            int wx = w + kx - 1;
            if (wx < 0 || wx >= Wd) continue;
            acc = fmaf(x[((size_t)(b * Hh + hy) * Wd + wx) * Cc + c],
                       wdw[(ky * 3 + kx) * Cc + c], acc);
        }
    }
    out[idx] = acc / (1.f + expf(-acc));   // SiLU
}

// ---------------------------------------------------------------------------
// Fused softmax + deformable bilinear sampling.
// One block per pixel, 192 threads. Warp g handles group g (GC=32 channels),
// so each gather is one coalesced 128B segment.
// ---------------------------------------------------------------------------
__global__ __launch_bounds__(192) void deform_sample(
    const float* __restrict__ xproj, const float* __restrict__ off,
    const float* __restrict__ msk, float* __restrict__ out)
{
    const int pix = blockIdx.x;
    const int tid = threadIdx.x;

    __shared__ float s_off[NOFF];
    __shared__ float s_m[NMSK];
    __shared__ float s_ph[NMSK], s_pw[NMSK], s_a[NMSK];

    if (tid < NOFF) s_off[tid] = off[(size_t)pix * NOFF + tid];
    if (tid >= 128 && tid < 128 + NMSK) s_m[tid - 128] = msk[(size_t)pix * NMSK + (tid - 128)];
    __syncthreads();

    const int w = pix % Wd;
    const int h = (pix / Wd) % Hh;
    const int b = pix / (Wd * Hh);

    if (tid < NMSK) {
        int k = tid % KK2;
        float ri = (float)(k / 3 - 1);
        float rj = (float)(k % 3 - 1);
        float ph = (float)h + ri + s_off[tid * 2 + 0] * 0.1f;
        float pw = (float)w + rj + s_off[tid * 2 + 1] * 0.1f;
        s_ph[tid] = fminf(fmaxf(ph, 0.f), (float)(Hh - 1));
        s_pw[tid] = fminf(fmaxf(pw, 0.f), (float)(Wd - 1));
    }
    if (tid >= 64 && tid < 64 + Gg) {
        int g = tid - 64;
        float mx = -1e30f;
#pragma unroll
        for (int k = 0; k < KK2; k++) mx = fmaxf(mx, s_m[g * KK2 + k]);
        float e[KK2], sum = 0.f;
#pragma unroll
        for (int k = 0; k < KK2; k++) { e[k] = expf(s_m[g * KK2 + k] - mx); sum += e[k]; }
        float inv = 1.f / sum;
#pragma unroll
        for (int k = 0; k < KK2; k++) s_a[g * KK2 + k] = e[k] * inv;
    }
    __syncthreads();

    const int g = tid >> 5;        // warp == group (GC = 32)
    const int cc = tid & 31;
    const float* xb = xproj + (size_t)b * Hh * Wd * Cc + g * GC + cc;

    float acc = 0.f;
#pragma unroll
    for (int k = 0; k < KK2; k++) {
        float ph = s_ph[g * KK2 + k];
        float pw = s_pw[g * KK2 + k];
        float a  = s_a [g * KK2 + k];
        int hf = (int)ph;
        int wf = (int)pw;
        int hc = min(hf + 1, Hh - 1);
        int wc = min(wf + 1, Wd - 1);
        float hw = ph - (float)hf;
        float ww = pw - (float)wf;
        float v00 = xb[((size_t)hf * Wd + wf) * Cc];
        float v01 = xb[((size_t)hf * Wd + wc) * Cc];
        float v10 = xb[((size_t)hc * Wd + wf) * Cc];
        float v11 = xb[((size_t)hc * Wd + wc) * Cc];
        float top = fmaf(ww, v01 - v00, v00);
        float bot = fmaf(ww, v11 - v10, v10);
        acc = fmaf(a, fmaf(hw, bot - top, top), acc);
    }
    out[(size_t)pix * Cc + tid] = acc;
}

// ---------------------------------------------------------------------------
// Launch
// ---------------------------------------------------------------------------
extern "C" void kernel_launch(void* const* d_in, const int* in_sizes, int n_in,
                              void* d_out, int out_size)
{
    const float* x      = (const float*)d_in[0];
    const float* w_in   = (const float*)d_in[1];
    const float* b_in   = (const float*)d_in[2];
    const float* w_dw   = (const float*)d_in[3];
    const float* b_dw   = (const float*)d_in[4];
    const float* w_pw   = (const float*)d_in[5];   // (1,1,C,C) == [C,C]
    const float* b_pw   = (const float*)d_in[6];
    const float* w_off  = (const float*)d_in[7];
    const float* b_off  = (const float*)d_in[8];
    const float* w_mask = (const float*)d_in[9];
    const float* b_mask = (const float*)d_in[10];
    const float* w_out  = (const float*)d_in[11];
    const float* b_out  = (const float*)d_in[12];
    float* out = (float*)d_out;

    float *xproj, *xd, *tmp, *offp, *mskp;
    cudaGetSymbolAddress((void**)&xproj, g_xproj);
    cudaGetSymbolAddress((void**)&xd,    g_xd);
    cudaGetSymbolAddress((void**)&tmp,   g_tmp);
    cudaGetSymbolAddress((void**)&offp,  g_off);
    cudaGetSymbolAddress((void**)&mskp,  g_msk);

    const int M = M_PIX, K = Cc;
    dim3 blk(256);
    dim3 grid_c((Cc + 63) / 64, M / 128);       // N = 192 -> 3 col tiles
    dim3 grid_o((NOFF + 63) / 64, M / 128);     // N = 108 -> 2 col tiles
    dim3 grid_m((NMSK + 63) / 64, M / 128);     // N = 54  -> 1 col tile

    // 1. x_proj = x @ w_in + b_in
    sgemm_bias<<<grid_c, blk>>>(x, w_in, b_in, xproj, M, Cc, K);
    // 2. depthwise 3x3 + SiLU on x
    {
        size_t n = (size_t)M_PIX * Cc;
        dw_silu<<<(unsigned)((n + 255) / 256), 256>>>(x, w_dw, b_dw, tmp);
    }
    // 3. xd = dw_out @ w_pw + b_pw
    sgemm_bias<<<grid_c, blk>>>(tmp, w_pw, b_pw, xd, M, Cc, K);
    // 4. offsets = xd @ w_off + b_off
    sgemm_bias<<<grid_o, blk>>>(xd, w_off, b_off, offp, M, NOFF, K);
    // 5. mask logits = xd @ w_mask + b_mask
    sgemm_bias<<<grid_m, blk>>>(xd, w_mask, b_mask, mskp, M, NMSK, K);
    // 6. softmax + deformable bilinear sampling -> tmp (reused)
    deform_sample<<<M_PIX, 192>>>(xproj, offp, mskp, tmp);
    // 7. out = sampled @ w_out + b_out
    sgemm_bias<<<grid_c, blk>>>(tmp, w_out, b_out, out, M, Cc, K);
}